// round 1
// baseline (speedup 1.0000x reference)
#include <cuda_runtime.h>
#include <cuda_bf16.h>
#include <math.h>

// ---------------------------------------------------------------------------
// Mamba block: B=4, L=2048, dim=1024, d_inner=2048, d_state=16, K=4, dt_rank=64
// ---------------------------------------------------------------------------
#define BB      4
#define LL      2048
#define DIM     1024
#define DINNER  2048
#define DSTATE  16
#define DCONV   4
#define DTRANK  64
#define NTOK    (BB * LL)          // 8192
#define DBC_W   (DTRANK + 2 * DSTATE)  // 96

// Scratch (device globals; no allocation allowed)
__device__ float g_xn[(size_t)NTOK * DIM];          // 33.5 MB
__device__ float g_xz[(size_t)NTOK * 2 * DINNER];   // 134 MB
__device__ float g_xi[(size_t)NTOK * DINNER];       // 67 MB   (post conv+silu)
__device__ float g_dbc[(size_t)NTOK * DBC_W];       // 3.1 MB
__device__ float g_delta[(size_t)NTOK * DINNER];    // 67 MB
__device__ float g_gated[(size_t)NTOK * DINNER];    // 67 MB

// ---------------------------------------------------------------------------
// RMSNorm: one block per token
// ---------------------------------------------------------------------------
__global__ void rmsnorm_kernel(const float* __restrict__ x,
                               const float* __restrict__ w,
                               float* __restrict__ xn) {
    int t = blockIdx.x;
    const float* xr = x + (size_t)t * DIM;
    float s = 0.f;
    for (int i = threadIdx.x; i < DIM; i += 256) {
        float v = xr[i];
        s += v * v;
    }
    // reduce within warp
    #pragma unroll
    for (int off = 16; off > 0; off >>= 1)
        s += __shfl_xor_sync(0xffffffffu, s, off);
    __shared__ float red[8];
    int wid = threadIdx.x >> 5;
    if ((threadIdx.x & 31) == 0) red[wid] = s;
    __syncthreads();
    __shared__ float sscale;
    if (threadIdx.x == 0) {
        float tot = 0.f;
        #pragma unroll
        for (int i = 0; i < 8; i++) tot += red[i];
        sscale = rsqrtf(tot * (1.0f / DIM) + 1e-5f);
    }
    __syncthreads();
    float scale = sscale;
    float* xo = xn + (size_t)t * DIM;
    for (int i = threadIdx.x; i < DIM; i += 256)
        xo[i] = xr[i] * scale * w[i];
}

// ---------------------------------------------------------------------------
// SGEMM: C[M,N] = A[M,K] (row stride lda) @ W[K,N]
// mode 0: plain   mode 1: softplus(acc + bias[n])   mode 2: acc + res[m*N+n]
// 128x128 block tile, BK=16, 256 threads, 8x8 per thread
// Requires: M % 128 == 0, K % 16 == 0, N % 4 == 0 (column-guarded for N<tile)
// ---------------------------------------------------------------------------
#define GBM 128
#define GBN 128
#define GBK 16
__global__ __launch_bounds__(256, 2)
void sgemm_kernel(const float* __restrict__ A, int lda,
                  const float* __restrict__ W,
                  float* __restrict__ C,
                  int M, int N, int K,
                  int mode, const float* __restrict__ extra) {
    __shared__ float As[GBK][GBM];
    __shared__ float Bs[GBK][GBN];

    int row0 = blockIdx.y * GBM;
    int col0 = blockIdx.x * GBN;
    int tid  = threadIdx.x;
    int tx = tid & 15;       // 0..15 -> N
    int ty = tid >> 4;       // 0..15 -> M

    float acc[8][8];
    #pragma unroll
    for (int i = 0; i < 8; i++)
        #pragma unroll
        for (int j = 0; j < 8; j++) acc[i][j] = 0.f;

    for (int k0 = 0; k0 < K; k0 += GBK) {
        // Load A tile: 128x16 = 512 float4, 2 per thread (store transposed)
        #pragma unroll
        for (int jj = 0; jj < 2; jj++) {
            int i = tid * 2 + jj;
            int r = i >> 2;
            int cc = (i & 3) * 4;
            float4 v = *(const float4*)(A + (size_t)(row0 + r) * lda + k0 + cc);
            As[cc + 0][r] = v.x;
            As[cc + 1][r] = v.y;
            As[cc + 2][r] = v.z;
            As[cc + 3][r] = v.w;
        }
        // Load W tile: 16x128 = 512 float4, 2 per thread (guard columns)
        #pragma unroll
        for (int jj = 0; jj < 2; jj++) {
            int i = tid * 2 + jj;
            int r = i >> 5;
            int cc = (i & 31) * 4;
            int col = col0 + cc;
            float4 v = make_float4(0.f, 0.f, 0.f, 0.f);
            if (col < N)
                v = *(const float4*)(W + (size_t)(k0 + r) * N + col);
            *(float4*)&Bs[r][cc] = v;
        }
        __syncthreads();

        #pragma unroll
        for (int kk = 0; kk < GBK; kk++) {
            float a[8], b[8];
            #pragma unroll
            for (int i = 0; i < 8; i++) a[i] = As[kk][ty * 8 + i];
            #pragma unroll
            for (int j = 0; j < 8; j++) b[j] = Bs[kk][tx * 8 + j];
            #pragma unroll
            for (int i = 0; i < 8; i++)
                #pragma unroll
                for (int j = 0; j < 8; j++)
                    acc[i][j] = fmaf(a[i], b[j], acc[i][j]);
        }
        __syncthreads();
    }

    // Epilogue
    #pragma unroll
    for (int i = 0; i < 8; i++) {
        int r = row0 + ty * 8 + i;
        #pragma unroll
        for (int j = 0; j < 8; j++) {
            int c = col0 + tx * 8 + j;
            if (c < N) {
                float v = acc[i][j];
                if (mode == 1) {
                    v += extra[c];
                    v = (v > 20.f) ? v : log1pf(__expf(v));  // softplus
                } else if (mode == 2) {
                    v += extra[(size_t)r * N + c];
                }
                C[(size_t)r * N + c] = v;
            }
        }
    }
}

// ---------------------------------------------------------------------------
// Causal depthwise conv (K=4) + bias + SiLU.  Reads xi part of xz.
// ---------------------------------------------------------------------------
__global__ void conv_silu_kernel(const float* __restrict__ xz,
                                 const float* __restrict__ conv_w,
                                 const float* __restrict__ conv_b,
                                 float* __restrict__ xi_out) {
    size_t idx = (size_t)blockIdx.x * blockDim.x + threadIdx.x;
    if (idx >= (size_t)NTOK * DINNER) return;
    int c = (int)(idx % DINNER);
    int t = (int)(idx / DINNER);   // b*L + l
    int l = t % LL;
    int tb = t - l;                // b*L
    float acc = conv_b[c];
    #pragma unroll
    for (int k = 0; k < DCONV; k++) {
        int ls = l - (DCONV - 1) + k;
        if (ls >= 0)
            acc += xz[(size_t)(tb + ls) * (2 * DINNER) + c] * conv_w[c * DCONV + k];
    }
    // SiLU
    float s = acc / (1.f + __expf(-acc));
    xi_out[idx] = s;
}

// ---------------------------------------------------------------------------
// Selective scan. One thread per channel; 16 states in registers.
// Fuses D-skip, output gate silu(z). Writes gated y.
// ---------------------------------------------------------------------------
__global__ __launch_bounds__(128, 1)
void scan_kernel(const float* __restrict__ dbc,
                 const float* __restrict__ delta,
                 const float* __restrict__ xi,
                 const float* __restrict__ xz,
                 const float* __restrict__ A_log,
                 const float* __restrict__ Dp,
                 float* __restrict__ gated) {
    int blocks_per_b = DINNER / 128;
    int b     = blockIdx.x / blocks_per_b;
    int cbase = (blockIdx.x % blocks_per_b) * 128;
    int c     = cbase + threadIdx.x;
    int tidx  = threadIdx.x;

    float A[DSTATE];
    #pragma unroll
    for (int s = 0; s < DSTATE; s++)
        A[s] = -__expf(A_log[c * DSTATE + s]);
    float Dv = Dp[c];

    float h[DSTATE];
    #pragma unroll
    for (int s = 0; s < DSTATE; s++) h[s] = 0.f;

    __shared__ float bc[2][2 * DSTATE];

    size_t tok0 = (size_t)b * LL;

    // prefetch l = 0
    if (tidx < 2 * DSTATE)
        bc[0][tidx] = dbc[tok0 * DBC_W + DTRANK + tidx];
    float d  = delta[tok0 * DINNER + c];
    float xv = xi[tok0 * DINNER + c];
    float zv = xz[tok0 * (2 * DINNER) + DINNER + c];
    __syncthreads();

    for (int l = 0; l < LL; l++) {
        int buf  = l & 1;
        int nbuf = buf ^ 1;
        float dn = 0.f, xn2 = 0.f, zn = 0.f;
        if (l + 1 < LL) {
            size_t tn = tok0 + l + 1;
            if (tidx < 2 * DSTATE)
                bc[nbuf][tidx] = dbc[tn * DBC_W + DTRANK + tidx];
            dn  = delta[tn * DINNER + c];
            xn2 = xi[tn * DINNER + c];
            zn  = xz[tn * (2 * DINNER) + DINNER + c];
        }

        float dx = d * xv;
        float y = 0.f;
        #pragma unroll
        for (int s = 0; s < DSTATE; s++) {
            float dA = __expf(d * A[s]);
            h[s] = dA * h[s] + dx * bc[buf][s];
            y = fmaf(h[s], bc[buf][DSTATE + s], y);
        }
        float g  = y + xv * Dv;
        float sg = zv / (1.f + __expf(-zv));
        gated[(tok0 + l) * DINNER + c] = g * sg;

        __syncthreads();   // next buffer ready + current buffer consumed
        d = dn; xv = xn2; zv = zn;
    }
}

// ---------------------------------------------------------------------------
// Launch
// ---------------------------------------------------------------------------
extern "C" void kernel_launch(void* const* d_in, const int* in_sizes, int n_in,
                              void* d_out, int out_size) {
    const float* x        = (const float*)d_in[0];
    const float* rms_w    = (const float*)d_in[1];
    const float* in_proj  = (const float*)d_in[2];
    const float* conv_w   = (const float*)d_in[3];
    const float* conv_b   = (const float*)d_in[4];
    const float* x_proj   = (const float*)d_in[5];
    const float* dt_w     = (const float*)d_in[6];
    const float* dt_b     = (const float*)d_in[7];
    const float* A_log    = (const float*)d_in[8];
    const float* Dp       = (const float*)d_in[9];
    const float* out_proj = (const float*)d_in[10];
    float* out = (float*)d_out;

    float *xn, *xz, *xi, *dbc, *delta, *gated;
    cudaGetSymbolAddress((void**)&xn,    g_xn);
    cudaGetSymbolAddress((void**)&xz,    g_xz);
    cudaGetSymbolAddress((void**)&xi,    g_xi);
    cudaGetSymbolAddress((void**)&dbc,   g_dbc);
    cudaGetSymbolAddress((void**)&delta, g_delta);
    cudaGetSymbolAddress((void**)&gated, g_gated);

    // 1. RMSNorm
    rmsnorm_kernel<<<NTOK, 256>>>(x, rms_w, xn);

    // 2. xz = xn @ in_proj   [8192 x 4096], K=1024
    {
        dim3 grid((2 * DINNER + GBN - 1) / GBN, NTOK / GBM);
        sgemm_kernel<<<grid, 256>>>(xn, DIM, in_proj, xz,
                                    NTOK, 2 * DINNER, DIM, 0, nullptr);
    }

    // 3. conv + silu -> xi
    {
        size_t n = (size_t)NTOK * DINNER;
        conv_silu_kernel<<<(unsigned)((n + 255) / 256), 256>>>(xz, conv_w, conv_b, xi);
    }

    // 4. dbc = xi @ x_proj   [8192 x 96], K=2048
    {
        dim3 grid((DBC_W + GBN - 1) / GBN, NTOK / GBM);
        sgemm_kernel<<<grid, 256>>>(xi, DINNER, x_proj, dbc,
                                    NTOK, DBC_W, DINNER, 0, nullptr);
    }

    // 5. delta = softplus(dt @ dt_w + dt_b)   [8192 x 2048], K=64 (dt = dbc[:, :64])
    {
        dim3 grid((DINNER + GBN - 1) / GBN, NTOK / GBM);
        sgemm_kernel<<<grid, 256>>>(dbc, DBC_W, dt_w, delta,
                                    NTOK, DINNER, DTRANK, 1, dt_b);
    }

    // 6. selective scan + D skip + gate
    scan_kernel<<<BB * (DINNER / 128), 128>>>(dbc, delta, xi, xz, A_log, Dp, gated);

    // 7. out = x + gated @ out_proj   [8192 x 1024], K=2048
    {
        dim3 grid((DIM + GBN - 1) / GBN, NTOK / GBM);
        sgemm_kernel<<<grid, 256>>>(gated, DINNER, out_proj, out,
                                    NTOK, DIM, DINNER, 2, x);
    }
}

// round 3
// speedup vs baseline: 1.5707x; 1.5707x over previous
#include <cuda_runtime.h>
#include <cuda_bf16.h>
#include <math.h>
#include <stdint.h>

// ---------------------------------------------------------------------------
// Mamba block: B=4, L=2048, dim=1024, d_inner=2048, d_state=16, K=4, dt_rank=64
// NOTE: harness compiles PTX at baseline .target sm_103 (no 'a'), so tcgen05 /
// TMA-tensor are unavailable. Use sm_80-baseline ldmatrix + mma.sync (HMMA).
// ---------------------------------------------------------------------------
#define BB      4
#define LL      2048
#define DIM     1024
#define DINNER  2048
#define DSTATE  16
#define DCONV   4
#define DTRANK  64
#define NTOK    (BB * LL)              // 8192
#define DBC_W   (DTRANK + 2 * DSTATE)  // 96

// ---------------------------------------------------------------------------
// Scratch (device globals; zero-initialized at module load)
// ---------------------------------------------------------------------------
__device__ float         g_xz[(size_t)NTOK * 2 * DINNER];
__device__ float         g_dbc[(size_t)NTOK * DBC_W];
__device__ float         g_delta[(size_t)NTOK * DINNER];
__device__ __nv_bfloat16 g_xnh[(size_t)NTOK * DIM];
__device__ __nv_bfloat16 g_xnl[(size_t)NTOK * DIM];
__device__ __nv_bfloat16 g_xih[(size_t)NTOK * DINNER];
__device__ __nv_bfloat16 g_xil[(size_t)NTOK * DINNER];
__device__ __nv_bfloat16 g_dth[(size_t)NTOK * DTRANK];
__device__ __nv_bfloat16 g_dtl[(size_t)NTOK * DTRANK];
__device__ __nv_bfloat16 g_gh[(size_t)NTOK * DINNER];
__device__ __nv_bfloat16 g_gl[(size_t)NTOK * DINNER];
// transposed weights [N, K] bf16 hi/lo.  x_proj dest padded to 128 rows
// (rows 96..127 stay zero from static init — never written).
__device__ __nv_bfloat16 g_ipTh[(size_t)(2 * DINNER) * DIM];
__device__ __nv_bfloat16 g_ipTl[(size_t)(2 * DINNER) * DIM];
__device__ __nv_bfloat16 g_xpTh[(size_t)128 * DINNER];
__device__ __nv_bfloat16 g_xpTl[(size_t)128 * DINNER];
__device__ __nv_bfloat16 g_dwTh[(size_t)DINNER * DTRANK];
__device__ __nv_bfloat16 g_dwTl[(size_t)DINNER * DTRANK];
__device__ __nv_bfloat16 g_opTh[(size_t)DIM * DINNER];
__device__ __nv_bfloat16 g_opTl[(size_t)DIM * DINNER];

// ---------------------------------------------------------------------------
// Small PTX helpers (all sm_80-baseline)
// ---------------------------------------------------------------------------
__device__ __forceinline__ uint32_t smem_u32(const void* p) {
    uint32_t a;
    asm("{ .reg .u64 t; cvta.to.shared.u64 t, %1; cvt.u32.u64 %0, t; }" : "=r"(a) : "l"(p));
    return a;
}
__device__ __forceinline__ void cp16(uint32_t dst, const void* src) {
    asm volatile("cp.async.cg.shared.global [%0], [%1], 16;" :: "r"(dst), "l"(src));
}
#define CP_COMMIT() asm volatile("cp.async.commit_group;" ::: "memory")
#define CP_WAIT0()  asm volatile("cp.async.wait_group 0;"  ::: "memory")

#define LDSM4(r, a) \
    asm volatile("ldmatrix.sync.aligned.m8n8.x4.shared.b16 {%0,%1,%2,%3}, [%4];" \
        : "=r"((r)[0]), "=r"((r)[1]), "=r"((r)[2]), "=r"((r)[3]) : "r"(a))

#define MMA16816(d, a, b0, b1) \
    asm volatile("mma.sync.aligned.m16n8k16.row.col.f32.bf16.bf16.f32 " \
        "{%0,%1,%2,%3}, {%4,%5,%6,%7}, {%8,%9}, {%0,%1,%2,%3};" \
        : "+f"((d)[0]), "+f"((d)[1]), "+f"((d)[2]), "+f"((d)[3]) \
        : "r"((a)[0]), "r"((a)[1]), "r"((a)[2]), "r"((a)[3]), "r"(b0), "r"(b1))

// ---------------------------------------------------------------------------
// Weight transpose + hi/lo split: W[R,C] fp32 -> T[C,R] bf16 hi/lo
// ---------------------------------------------------------------------------
__global__ void transpose_split(const float* __restrict__ W,
                                __nv_bfloat16* __restrict__ Th,
                                __nv_bfloat16* __restrict__ Tl,
                                int R, int C) {
    __shared__ float t[32][33];
    int c0 = blockIdx.x * 32, r0 = blockIdx.y * 32;
    int c = c0 + threadIdx.x;
    for (int i = threadIdx.y; i < 32; i += 8) {
        int r = r0 + i;
        if (r < R && c < C) t[i][threadIdx.x] = W[(size_t)r * C + c];
    }
    __syncthreads();
    int k = r0 + threadIdx.x;
    for (int i = threadIdx.y; i < 32; i += 8) {
        int n = c0 + i;
        if (n < C && k < R) {
            float v = t[threadIdx.x][i];
            __nv_bfloat16 h = __float2bfloat16(v);
            Th[(size_t)n * R + k] = h;
            Tl[(size_t)n * R + k] = __float2bfloat16(v - __bfloat162float(h));
        }
    }
}

// ---------------------------------------------------------------------------
// RMSNorm -> bf16 hi/lo
// ---------------------------------------------------------------------------
__global__ void rmsnorm_kernel(const float* __restrict__ x,
                               const float* __restrict__ w,
                               __nv_bfloat16* __restrict__ xnh,
                               __nv_bfloat16* __restrict__ xnl) {
    int t = blockIdx.x;
    const float* xr = x + (size_t)t * DIM;
    float s = 0.f;
    for (int i = threadIdx.x; i < DIM; i += 256) { float v = xr[i]; s += v * v; }
    #pragma unroll
    for (int off = 16; off > 0; off >>= 1) s += __shfl_xor_sync(0xffffffffu, s, off);
    __shared__ float red[8];
    int wid = threadIdx.x >> 5;
    if ((threadIdx.x & 31) == 0) red[wid] = s;
    __syncthreads();
    __shared__ float sscale;
    if (threadIdx.x == 0) {
        float tot = 0.f;
        #pragma unroll
        for (int i = 0; i < 8; i++) tot += red[i];
        sscale = rsqrtf(tot * (1.0f / DIM) + 1e-5f);
    }
    __syncthreads();
    float scale = sscale;
    for (int i = threadIdx.x; i < DIM; i += 256) {
        float v = xr[i] * scale * w[i];
        __nv_bfloat16 h = __float2bfloat16(v);
        xnh[(size_t)t * DIM + i] = h;
        xnl[(size_t)t * DIM + i] = __float2bfloat16(v - __bfloat162float(h));
    }
}

// ---------------------------------------------------------------------------
// mma.sync split-bf16 GEMM: C[M,N] = (Ah+Al)[M,K] @ (Bh+Bl)[N,K]^T
// 128x128x32 tile, 256 threads (8 warps as 4Mx2N, warp tile 32x64).
// Smem tiles [128][40] bf16 (pad 40 => conflict-free ldmatrix), hi+lo for A,B.
// Double-buffered via cp.async.  3 MMAs per tile (hh + hl + lh) into fp32 acc.
// MODE 0: plain  1: softplus(acc+bias[n])  2: acc+res[r*N+c]
// MODE 3: write dbc (guard c<N) and also dt hi/lo for c<64
// ---------------------------------------------------------------------------
#define TS   10240                    // bytes per [128][40] bf16 tile
#define BUFB (4 * TS)                 // 40960 per buffer
#define SMEM_GEMM (2 * BUFB)          // 81920

template<int MODE>
__global__ void __launch_bounds__(256)
mma_gemm(const __nv_bfloat16* __restrict__ Ah, const __nv_bfloat16* __restrict__ Al,
         const __nv_bfloat16* __restrict__ Bh, const __nv_bfloat16* __restrict__ Bl,
         float* __restrict__ C, int N, int K,
         const float* __restrict__ extra,
         __nv_bfloat16* __restrict__ dth, __nv_bfloat16* __restrict__ dtl) {
    extern __shared__ char smem[];
    const uint32_t sb = smem_u32(smem);
    const int tid  = threadIdx.x;
    const int lane = tid & 31;
    const int wid  = tid >> 5;
    const int wm = (wid & 3) * 32;
    const int wn = (wid >> 2) * 64;
    const int row0 = blockIdx.y * 128;
    const int col0 = blockIdx.x * 128;

    // load one k-chunk (32) of all 4 tiles into buffer `b`
    auto load_chunk = [&](int b, int k0) {
        uint32_t base = sb + b * BUFB;
        #pragma unroll
        for (int u = 0; u < 2; u++) {
            int i = u * 256 + tid;
            int r = i >> 2, seg = i & 3;
            uint32_t d = base + r * 80 + seg * 16;
            size_t ga = (size_t)(row0 + r) * K + k0 + seg * 8;
            size_t gb = (size_t)(col0 + r) * K + k0 + seg * 8;
            cp16(d,              Ah + ga);
            cp16(d + TS,         Al + ga);
            cp16(d + 2 * TS,     Bh + gb);
            cp16(d + 3 * TS,     Bl + gb);
        }
        CP_COMMIT();
    };

    float acc[2][8][4];
    #pragma unroll
    for (int mi = 0; mi < 2; mi++)
        #pragma unroll
        for (int ni = 0; ni < 8; ni++)
            #pragma unroll
            for (int q = 0; q < 4; q++) acc[mi][ni][q] = 0.f;

    const int lrow = lane & 15;
    const int lkb  = lane >> 4;
    const int nchunks = K >> 5;

    load_chunk(0, 0);
    int buf = 0;
    for (int kc = 0; kc < nchunks; kc++) {
        CP_WAIT0();
        __syncthreads();
        if (kc + 1 < nchunks) load_chunk(buf ^ 1, (kc + 1) << 5);

        uint32_t base = sb + buf * BUFB;
        #pragma unroll
        for (int ks = 0; ks < 2; ks++) {
            uint32_t koff = (ks * 16 + lkb * 8) * 2;
            uint32_t ah[2][4], al[2][4];
            #pragma unroll
            for (int mi = 0; mi < 2; mi++) {
                uint32_t ra = base + (wm + mi * 16 + lrow) * 80 + koff;
                LDSM4(ah[mi], ra);
                LDSM4(al[mi], ra + TS);
            }
            uint32_t bh[4][4], bl[4][4];
            #pragma unroll
            for (int p = 0; p < 4; p++) {
                uint32_t rb = base + 2 * TS + (wn + p * 16 + lrow) * 80 + koff;
                LDSM4(bh[p], rb);
                LDSM4(bl[p], rb + TS);
            }
            #pragma unroll
            for (int mi = 0; mi < 2; mi++)
                #pragma unroll
                for (int p = 0; p < 4; p++)
                    #pragma unroll
                    for (int hb = 0; hb < 2; hb++) {
                        int ni = p * 2 + hb;
                        MMA16816(acc[mi][ni], ah[mi], bh[p][hb], bh[p][hb + 2]);
                        MMA16816(acc[mi][ni], ah[mi], bl[p][hb], bl[p][hb + 2]);
                        MMA16816(acc[mi][ni], al[mi], bh[p][hb], bh[p][hb + 2]);
                    }
        }
        __syncthreads();
        buf ^= 1;
    }

    // epilogue: thread owns (r, c), (r, c+1) and (r+8, c), (r+8, c+1) per tile
    const int rb = row0 + wm + (lane >> 2);
    const int cb = col0 + wn + (lane & 3) * 2;
    #pragma unroll
    for (int mi = 0; mi < 2; mi++)
        #pragma unroll
        for (int ni = 0; ni < 8; ni++) {
            int c = cb + ni * 8;
            if (c >= N) continue;
            #pragma unroll
            for (int half = 0; half < 2; half++) {
                int r = rb + mi * 16 + half * 8;
                float v0 = acc[mi][ni][half * 2 + 0];
                float v1 = acc[mi][ni][half * 2 + 1];
                if (MODE == 1) {
                    v0 += extra[c];     v1 += extra[c + 1];
                    v0 = (v0 > 20.f) ? v0 : log1pf(__expf(v0));
                    v1 = (v1 > 20.f) ? v1 : log1pf(__expf(v1));
                } else if (MODE == 2) {
                    const float2 res = *(const float2*)(extra + (size_t)r * N + c);
                    v0 += res.x; v1 += res.y;
                }
                *(float2*)(C + (size_t)r * N + c) = make_float2(v0, v1);
                if (MODE == 3 && c < DTRANK) {
                    __nv_bfloat16 h0 = __float2bfloat16(v0);
                    __nv_bfloat16 h1 = __float2bfloat16(v1);
                    dth[(size_t)r * DTRANK + c]     = h0;
                    dth[(size_t)r * DTRANK + c + 1] = h1;
                    dtl[(size_t)r * DTRANK + c]     = __float2bfloat16(v0 - __bfloat162float(h0));
                    dtl[(size_t)r * DTRANK + c + 1] = __float2bfloat16(v1 - __bfloat162float(h1));
                }
            }
        }
}

// ---------------------------------------------------------------------------
// Causal depthwise conv (K=4) + bias + SiLU -> xi hi/lo bf16
// ---------------------------------------------------------------------------
__global__ void conv_silu_kernel(const float* __restrict__ xz,
                                 const float* __restrict__ conv_w,
                                 const float* __restrict__ conv_b,
                                 __nv_bfloat16* __restrict__ xih,
                                 __nv_bfloat16* __restrict__ xil) {
    size_t idx = (size_t)blockIdx.x * blockDim.x + threadIdx.x;
    if (idx >= (size_t)NTOK * DINNER) return;
    int c = (int)(idx % DINNER);
    int t = (int)(idx / DINNER);
    int l = t % LL;
    int tb = t - l;
    float acc = conv_b[c];
    #pragma unroll
    for (int k = 0; k < DCONV; k++) {
        int ls = l - (DCONV - 1) + k;
        if (ls >= 0)
            acc += xz[(size_t)(tb + ls) * (2 * DINNER) + c] * conv_w[c * DCONV + k];
    }
    float s = acc / (1.f + __expf(-acc));
    __nv_bfloat16 h = __float2bfloat16(s);
    xih[idx] = h;
    xil[idx] = __float2bfloat16(s - __bfloat162float(h));
}

// ---------------------------------------------------------------------------
// Selective scan. 1 thread/channel, 64-thread blocks (128 blocks).
// Per-warp B/C staging (no block barrier).  Fast path: when A[s]=(s+1)*A[0]
// (S4D-real init), exp(d*A[s]) = E^(s+1) with E=exp(d*A[0]) -> 1 MUFU/step.
// Fuses D skip + silu(z) gate; writes gated hi/lo bf16.
// ---------------------------------------------------------------------------
__global__ __launch_bounds__(64, 1)
void scan_kernel(const float* __restrict__ dbc,
                 const float* __restrict__ delta,
                 const __nv_bfloat16* __restrict__ xih,
                 const __nv_bfloat16* __restrict__ xil,
                 const float* __restrict__ xz,
                 const float* __restrict__ A_log,
                 const float* __restrict__ Dp,
                 __nv_bfloat16* __restrict__ gh,
                 __nv_bfloat16* __restrict__ gl) {
    const int blocks_per_b = DINNER / 64;
    const int b    = blockIdx.x / blocks_per_b;
    const int c    = (blockIdx.x % blocks_per_b) * 64 + threadIdx.x;
    const int wid  = threadIdx.x >> 5;
    const int lane = threadIdx.x & 31;

    float A[DSTATE];
    #pragma unroll
    for (int s = 0; s < DSTATE; s++) A[s] = -__expf(A_log[c * DSTATE + s]);
    const float a1 = A[0];
    bool pat = true;
    #pragma unroll
    for (int s = 0; s < DSTATE; s++)
        pat = pat && (fabsf(A[s] - (float)(s + 1) * a1) <= 1e-5f * fabsf(A[s]));
    const float Dv = Dp[c];
    float h[DSTATE];
    #pragma unroll
    for (int s = 0; s < DSTATE; s++) h[s] = 0.f;

    __shared__ float bc[2][2][2 * DSTATE];   // [warp][buf][B:16 | C:16]
    size_t tok0 = (size_t)b * LL;

    bc[wid][0][lane] = dbc[tok0 * DBC_W + DTRANK + lane];
    float d  = delta[tok0 * DINNER + c];
    float xv = __bfloat162float(xih[tok0 * DINNER + c]) + __bfloat162float(xil[tok0 * DINNER + c]);
    float zv = xz[tok0 * (2 * DINNER) + DINNER + c];
    __syncwarp();

    for (int l = 0; l < LL; l++) {
        int bufi = l & 1, nbuf = bufi ^ 1;
        float dn = 0.f, xn2 = 0.f, zn = 0.f;
        if (l + 1 < LL) {
            size_t tn = tok0 + l + 1;
            bc[wid][nbuf][lane] = dbc[tn * DBC_W + DTRANK + lane];
            dn  = delta[tn * DINNER + c];
            xn2 = __bfloat162float(xih[tn * DINNER + c]) + __bfloat162float(xil[tn * DINNER + c]);
            zn  = xz[tn * (2 * DINNER) + DINNER + c];
        }
        const float* Bv = bc[wid][bufi];
        const float* Cv = bc[wid][bufi] + DSTATE;
        float dx = d * xv;
        float y = 0.f;
        if (pat) {
            float E = __expf(d * a1);
            float p = E;
            #pragma unroll
            for (int s = 0; s < DSTATE; s++) {
                h[s] = p * h[s] + dx * Bv[s];
                y = fmaf(h[s], Cv[s], y);
                p *= E;
            }
        } else {
            #pragma unroll
            for (int s = 0; s < DSTATE; s++) {
                float dA = __expf(d * A[s]);
                h[s] = dA * h[s] + dx * Bv[s];
                y = fmaf(h[s], Cv[s], y);
            }
        }
        float g  = y + xv * Dv;
        float sg = zv / (1.f + __expf(-zv));
        float outv = g * sg;
        __nv_bfloat16 hh = __float2bfloat16(outv);
        gh[(tok0 + l) * DINNER + c] = hh;
        gl[(tok0 + l) * DINNER + c] = __float2bfloat16(outv - __bfloat162float(hh));
        __syncwarp();
        d = dn; xv = xn2; zv = zn;
    }
}

// ---------------------------------------------------------------------------
// Launch
// ---------------------------------------------------------------------------
extern "C" void kernel_launch(void* const* d_in, const int* in_sizes, int n_in,
                              void* d_out, int out_size) {
    const float* x        = (const float*)d_in[0];
    const float* rms_w    = (const float*)d_in[1];
    const float* in_proj  = (const float*)d_in[2];
    const float* conv_w   = (const float*)d_in[3];
    const float* conv_b   = (const float*)d_in[4];
    const float* x_proj   = (const float*)d_in[5];
    const float* dt_w     = (const float*)d_in[6];
    const float* dt_b     = (const float*)d_in[7];
    const float* A_log    = (const float*)d_in[8];
    const float* Dp       = (const float*)d_in[9];
    const float* out_proj = (const float*)d_in[10];
    float* out = (float*)d_out;

    float *xz, *dbc, *delta;
    __nv_bfloat16 *xnh, *xnl, *xih, *xil, *dth, *dtl, *gh, *gl;
    __nv_bfloat16 *ipTh, *ipTl, *xpTh, *xpTl, *dwTh, *dwTl, *opTh, *opTl;
    cudaGetSymbolAddress((void**)&xz,    g_xz);
    cudaGetSymbolAddress((void**)&dbc,   g_dbc);
    cudaGetSymbolAddress((void**)&delta, g_delta);
    cudaGetSymbolAddress((void**)&xnh,   g_xnh);
    cudaGetSymbolAddress((void**)&xnl,   g_xnl);
    cudaGetSymbolAddress((void**)&xih,   g_xih);
    cudaGetSymbolAddress((void**)&xil,   g_xil);
    cudaGetSymbolAddress((void**)&dth,   g_dth);
    cudaGetSymbolAddress((void**)&dtl,   g_dtl);
    cudaGetSymbolAddress((void**)&gh,    g_gh);
    cudaGetSymbolAddress((void**)&gl,    g_gl);
    cudaGetSymbolAddress((void**)&ipTh,  g_ipTh);
    cudaGetSymbolAddress((void**)&ipTl,  g_ipTl);
    cudaGetSymbolAddress((void**)&xpTh,  g_xpTh);
    cudaGetSymbolAddress((void**)&xpTl,  g_xpTl);
    cudaGetSymbolAddress((void**)&dwTh,  g_dwTh);
    cudaGetSymbolAddress((void**)&dwTl,  g_dwTl);
    cudaGetSymbolAddress((void**)&opTh,  g_opTh);
    cudaGetSymbolAddress((void**)&opTl,  g_opTl);

    cudaFuncSetAttribute(mma_gemm<0>, cudaFuncAttributeMaxDynamicSharedMemorySize, SMEM_GEMM);
    cudaFuncSetAttribute(mma_gemm<1>, cudaFuncAttributeMaxDynamicSharedMemorySize, SMEM_GEMM);
    cudaFuncSetAttribute(mma_gemm<2>, cudaFuncAttributeMaxDynamicSharedMemorySize, SMEM_GEMM);
    cudaFuncSetAttribute(mma_gemm<3>, cudaFuncAttributeMaxDynamicSharedMemorySize, SMEM_GEMM);

    // 0. weight prep (transpose + split)
    { dim3 g(2 * DINNER / 32, DIM / 32);   transpose_split<<<g, dim3(32, 8)>>>(in_proj,  ipTh, ipTl, DIM,    2 * DINNER); }
    { dim3 g(3, DINNER / 32);              transpose_split<<<g, dim3(32, 8)>>>(x_proj,   xpTh, xpTl, DINNER, DBC_W); }
    { dim3 g(DINNER / 32, DTRANK / 32);    transpose_split<<<g, dim3(32, 8)>>>(dt_w,     dwTh, dwTl, DTRANK, DINNER); }
    { dim3 g(DIM / 32, DINNER / 32);       transpose_split<<<g, dim3(32, 8)>>>(out_proj, opTh, opTl, DINNER, DIM); }

    // 1. RMSNorm -> xn hi/lo
    rmsnorm_kernel<<<NTOK, 256>>>(x, rms_w, xnh, xnl);

    // 2. xz = xn @ in_proj  [8192 x 4096], K=1024
    {
        dim3 grid(2 * DINNER / 128, NTOK / 128);
        mma_gemm<0><<<grid, 256, SMEM_GEMM>>>(xnh, xnl, ipTh, ipTl, xz,
                                              2 * DINNER, DIM, nullptr, nullptr, nullptr);
    }

    // 3. conv + silu -> xi hi/lo
    {
        size_t n = (size_t)NTOK * DINNER;
        conv_silu_kernel<<<(unsigned)((n + 255) / 256), 256>>>(xz, conv_w, conv_b, xih, xil);
    }

    // 4. dbc = xi @ x_proj  [8192 x 96], K=2048 ; also dt cols -> hi/lo bf16
    {
        dim3 grid(1, NTOK / 128);
        mma_gemm<3><<<grid, 256, SMEM_GEMM>>>(xih, xil, xpTh, xpTl, dbc,
                                              DBC_W, DINNER, nullptr, dth, dtl);
    }

    // 5. delta = softplus(dt @ dt_w + dt_b)  [8192 x 2048], K=64
    {
        dim3 grid(DINNER / 128, NTOK / 128);
        mma_gemm<1><<<grid, 256, SMEM_GEMM>>>(dth, dtl, dwTh, dwTl, delta,
                                              DINNER, DTRANK, dt_b, nullptr, nullptr);
    }

    // 6. selective scan + D skip + gate -> gated hi/lo
    scan_kernel<<<BB * (DINNER / 64), 64>>>(dbc, delta, xih, xil, xz, A_log, Dp, gh, gl);

    // 7. out = x + gated @ out_proj  [8192 x 1024], K=2048
    {
        dim3 grid(DIM / 128, NTOK / 128);
        mma_gemm<2><<<grid, 256, SMEM_GEMM>>>(gh, gl, opTh, opTl, out,
                                              DIM, DINNER, x, nullptr, nullptr);
    }
}

// round 4
// speedup vs baseline: 3.4858x; 2.2192x over previous
#include <cuda_runtime.h>
#include <cuda_fp16.h>
#include <math.h>
#include <stdint.h>

// ---------------------------------------------------------------------------
// Mamba block: B=4, L=2048, dim=1024, d_inner=2048, d_state=16, K=4, dt_rank=64
// Baseline sm_103 PTX only (no tcgen05/TMA) -> ldmatrix + mma.sync fp16 HMMA.
// Precision: weights split hi/lo fp16 (2 MMAs), activations single fp16,
// fp32 accumulate. Residual error ~ activation rounding ~1.5e-4 << 1e-3 gate.
// ---------------------------------------------------------------------------
#define BB      4
#define LL      2048
#define DIM     1024
#define DINNER  2048
#define DSTATE  16
#define DCONV   4
#define DTRANK  64
#define NTOK    (BB * LL)              // 8192
#define DBC_W   (DTRANK + 2 * DSTATE)  // 96

// ---------------------------------------------------------------------------
// Scratch (device globals; zero-initialized at module load)
// ---------------------------------------------------------------------------
__device__ float  g_xz[(size_t)NTOK * 2 * DINNER];
__device__ float  g_dbc[(size_t)NTOK * DBC_W];
__device__ float  g_delta[(size_t)NTOK * DINNER];
__device__ __half g_xn[(size_t)NTOK * DIM];
__device__ __half g_xi[(size_t)NTOK * DINNER];
__device__ __half g_dt[(size_t)NTOK * DTRANK];
__device__ __half g_g[(size_t)NTOK * DINNER];
// transposed weights [N, K] fp16 hi/lo; x_proj padded to 128 rows (96..127 zero)
__device__ __half g_ipTh[(size_t)(2 * DINNER) * DIM];
__device__ __half g_ipTl[(size_t)(2 * DINNER) * DIM];
__device__ __half g_xpTh[(size_t)128 * DINNER];
__device__ __half g_xpTl[(size_t)128 * DINNER];
__device__ __half g_dwTh[(size_t)DINNER * DTRANK];
__device__ __half g_dwTl[(size_t)DINNER * DTRANK];
__device__ __half g_opTh[(size_t)DIM * DINNER];
__device__ __half g_opTl[(size_t)DIM * DINNER];

// ---------------------------------------------------------------------------
// PTX helpers (sm_80-baseline)
// ---------------------------------------------------------------------------
__device__ __forceinline__ uint32_t smem_u32(const void* p) {
    uint32_t a;
    asm("{ .reg .u64 t; cvta.to.shared.u64 t, %1; cvt.u32.u64 %0, t; }" : "=r"(a) : "l"(p));
    return a;
}
__device__ __forceinline__ void cp16(uint32_t dst, const void* src) {
    asm volatile("cp.async.cg.shared.global [%0], [%1], 16;" :: "r"(dst), "l"(src));
}
#define CP_COMMIT() asm volatile("cp.async.commit_group;" ::: "memory")
#define CP_WAIT(n)  asm volatile("cp.async.wait_group %0;" :: "n"(n) : "memory")

#define LDSM4(r, a) \
    asm volatile("ldmatrix.sync.aligned.m8n8.x4.shared.b16 {%0,%1,%2,%3}, [%4];" \
        : "=r"((r)[0]), "=r"((r)[1]), "=r"((r)[2]), "=r"((r)[3]) : "r"(a))

#define MMA16816(d, a, b0, b1) \
    asm volatile("mma.sync.aligned.m16n8k16.row.col.f32.f16.f16.f32 " \
        "{%0,%1,%2,%3}, {%4,%5,%6,%7}, {%8,%9}, {%0,%1,%2,%3};" \
        : "+f"((d)[0]), "+f"((d)[1]), "+f"((d)[2]), "+f"((d)[3]) \
        : "r"((a)[0]), "r"((a)[1]), "r"((a)[2]), "r"((a)[3]), "r"(b0), "r"(b1))

// ---------------------------------------------------------------------------
// Weight transpose + hi/lo split: W[R,C] fp32 -> T[C,R] fp16 hi/lo
// ---------------------------------------------------------------------------
__global__ void transpose_split(const float* __restrict__ W,
                                __half* __restrict__ Th,
                                __half* __restrict__ Tl,
                                int R, int C) {
    __shared__ float t[32][33];
    int c0 = blockIdx.x * 32, r0 = blockIdx.y * 32;
    int c = c0 + threadIdx.x;
    for (int i = threadIdx.y; i < 32; i += 8) {
        int r = r0 + i;
        if (r < R && c < C) t[i][threadIdx.x] = W[(size_t)r * C + c];
    }
    __syncthreads();
    int k = r0 + threadIdx.x;
    for (int i = threadIdx.y; i < 32; i += 8) {
        int n = c0 + i;
        if (n < C && k < R) {
            float v = t[threadIdx.x][i];
            __half h = __float2half(v);
            Th[(size_t)n * R + k] = h;
            Tl[(size_t)n * R + k] = __float2half(v - __half2float(h));
        }
    }
}

// ---------------------------------------------------------------------------
// RMSNorm -> fp16
// ---------------------------------------------------------------------------
__global__ void rmsnorm_kernel(const float* __restrict__ x,
                               const float* __restrict__ w,
                               __half* __restrict__ xn) {
    int t = blockIdx.x;
    const float* xr = x + (size_t)t * DIM;
    float s = 0.f;
    for (int i = threadIdx.x; i < DIM; i += 256) { float v = xr[i]; s += v * v; }
    #pragma unroll
    for (int off = 16; off > 0; off >>= 1) s += __shfl_xor_sync(0xffffffffu, s, off);
    __shared__ float red[8];
    int wid = threadIdx.x >> 5;
    if ((threadIdx.x & 31) == 0) red[wid] = s;
    __syncthreads();
    __shared__ float sscale;
    if (threadIdx.x == 0) {
        float tot = 0.f;
        #pragma unroll
        for (int i = 0; i < 8; i++) tot += red[i];
        sscale = rsqrtf(tot * (1.0f / DIM) + 1e-5f);
    }
    __syncthreads();
    float scale = sscale;
    for (int i = threadIdx.x; i < DIM; i += 256)
        xn[(size_t)t * DIM + i] = __float2half(xr[i] * scale * w[i]);
}

// ---------------------------------------------------------------------------
// mma.sync fp16 GEMM: C[M,N] = A[M,K] @ (Bh+Bl)[N,K]^T, fp32 accumulate.
// 128x128x32 tile, 256 threads (8 warps: 4M x 2N, warp tile 32x64).
// Smem [128][40] fp16 per tile (stride 80B, conflict-free ldmatrix).
// 3-stage cp.async pipeline; 2 MMAs per fragment pair (a*bh + a*bl).
// MODE 0: plain  1: softplus(acc+bias[n])  2: acc+res[r*N+c]
// MODE 3: write dbc fp32 (guard c<N) and also dt fp16 for c<64
// ---------------------------------------------------------------------------
#define TSB   10240                   // bytes per [128][40] fp16 tile
#define STGB  (3 * TSB)               // 30720 per stage
#define SMEM_GEMM (3 * STGB)          // 92160 (3 stages)

template<int MODE>
__global__ void __launch_bounds__(256)
mma_gemm(const __half* __restrict__ A,
         const __half* __restrict__ Bh, const __half* __restrict__ Bl,
         float* __restrict__ C, int N, int K,
         const float* __restrict__ extra,
         __half* __restrict__ dt) {
    extern __shared__ char smem[];
    const uint32_t sb = smem_u32(smem);
    const int tid  = threadIdx.x;
    const int lane = tid & 31;
    const int wid  = tid >> 5;
    const int wm = (wid & 3) * 32;
    const int wn = (wid >> 2) * 64;
    const int row0 = blockIdx.y * 128;
    const int col0 = blockIdx.x * 128;

    auto load_stage = [&](int st, int k0) {
        uint32_t base = sb + st * STGB;
        #pragma unroll
        for (int u = 0; u < 2; u++) {
            int i = u * 256 + tid;          // 0..511
            int r = i >> 2, seg = i & 3;
            uint32_t d = base + r * 80 + seg * 16;
            size_t ga = (size_t)(row0 + r) * K + k0 + seg * 8;
            size_t gb = (size_t)(col0 + r) * K + k0 + seg * 8;
            cp16(d,           A  + ga);
            cp16(d + TSB,     Bh + gb);
            cp16(d + 2 * TSB, Bl + gb);
        }
    };

    float acc[2][8][4];
    #pragma unroll
    for (int mi = 0; mi < 2; mi++)
        #pragma unroll
        for (int ni = 0; ni < 8; ni++)
            #pragma unroll
            for (int q = 0; q < 4; q++) acc[mi][ni][q] = 0.f;

    const int lrow = lane & 15;
    const int lkb  = lane >> 4;
    const int nch = K >> 5;

    load_stage(0, 0);  CP_COMMIT();
    load_stage(1, 32); CP_COMMIT();

    int st = 0;
    for (int kc = 0; kc < nch; kc++) {
        CP_WAIT(1);                 // stage kc landed
        __syncthreads();
        // prefetch kc+2 into the stage consumed last iteration (always commit)
        if (kc + 2 < nch) load_stage((st + 2) % 3, (kc + 2) << 5);
        CP_COMMIT();

        uint32_t base = sb + st * STGB;
        #pragma unroll
        for (int ks = 0; ks < 2; ks++) {
            uint32_t koff = (ks * 16 + lkb * 8) * 2;
            uint32_t ah[2][4];
            #pragma unroll
            for (int mi = 0; mi < 2; mi++)
                LDSM4(ah[mi], base + (wm + mi * 16 + lrow) * 80 + koff);
            uint32_t bh[4][4], bl[4][4];
            #pragma unroll
            for (int p = 0; p < 4; p++) {
                uint32_t rb = base + TSB + (wn + p * 16 + lrow) * 80 + koff;
                LDSM4(bh[p], rb);
                LDSM4(bl[p], rb + TSB);
            }
            #pragma unroll
            for (int mi = 0; mi < 2; mi++)
                #pragma unroll
                for (int p = 0; p < 4; p++)
                    #pragma unroll
                    for (int hb = 0; hb < 2; hb++) {
                        int ni = p * 2 + hb;
                        MMA16816(acc[mi][ni], ah[mi], bh[p][hb], bh[p][hb + 2]);
                        MMA16816(acc[mi][ni], ah[mi], bl[p][hb], bl[p][hb + 2]);
                    }
        }
        st = (st + 1) % 3;
        // next iteration's CP_WAIT+sync protects the buffer we just consumed
    }

    const int rb = row0 + wm + (lane >> 2);
    const int cb = col0 + wn + (lane & 3) * 2;
    #pragma unroll
    for (int mi = 0; mi < 2; mi++)
        #pragma unroll
        for (int ni = 0; ni < 8; ni++) {
            int c = cb + ni * 8;
            if (c >= N) continue;
            #pragma unroll
            for (int half = 0; half < 2; half++) {
                int r = rb + mi * 16 + half * 8;
                float v0 = acc[mi][ni][half * 2 + 0];
                float v1 = acc[mi][ni][half * 2 + 1];
                if (MODE == 1) {
                    v0 += extra[c];     v1 += extra[c + 1];
                    v0 = (v0 > 20.f) ? v0 : log1pf(__expf(v0));
                    v1 = (v1 > 20.f) ? v1 : log1pf(__expf(v1));
                } else if (MODE == 2) {
                    const float2 res = *(const float2*)(extra + (size_t)r * N + c);
                    v0 += res.x; v1 += res.y;
                }
                *(float2*)(C + (size_t)r * N + c) = make_float2(v0, v1);
                if (MODE == 3 && c < DTRANK) {
                    dt[(size_t)r * DTRANK + c]     = __float2half(v0);
                    dt[(size_t)r * DTRANK + c + 1] = __float2half(v1);
                }
            }
        }
}

// ---------------------------------------------------------------------------
// Causal depthwise conv (K=4) + bias + SiLU -> xi fp16
// ---------------------------------------------------------------------------
__global__ void conv_silu_kernel(const float* __restrict__ xz,
                                 const float* __restrict__ conv_w,
                                 const float* __restrict__ conv_b,
                                 __half* __restrict__ xi) {
    size_t idx = (size_t)blockIdx.x * blockDim.x + threadIdx.x;
    if (idx >= (size_t)NTOK * DINNER) return;
    int c = (int)(idx % DINNER);
    int t = (int)(idx / DINNER);
    int l = t % LL;
    int tb = t - l;
    float acc = conv_b[c];
    #pragma unroll
    for (int k = 0; k < DCONV; k++) {
        int ls = l - (DCONV - 1) + k;
        if (ls >= 0)
            acc += xz[(size_t)(tb + ls) * (2 * DINNER) + c] * conv_w[c * DCONV + k];
    }
    float s = acc / (1.f + __expf(-acc));
    xi[idx] = __float2half(s);
}

// ---------------------------------------------------------------------------
// Selective scan. 1 thread/channel, 64-thread blocks (128 blocks).
// Chunked cp.async staging (CHUNK=16 steps, 4 stages) -> loads fully
// pipelined; compute-bound.  Fast path when A[s]=(s+1)*A[0] (S4D-real init):
// exp powers via repeated squaring (depth ~4).  Fuses D skip + silu(z) gate.
// ---------------------------------------------------------------------------
#define SCHUNK 16
#define SSTG   12288                   // delta 4K | z 4K | bc 2K | xi 2K
#define SCAN_SMEM (4 * SSTG)           // 49152

__global__ __launch_bounds__(64, 1)
void scan_kernel(const float* __restrict__ dbc,
                 const float* __restrict__ delta,
                 const __half* __restrict__ xi,
                 const float* __restrict__ xz,
                 const float* __restrict__ A_log,
                 const float* __restrict__ Dp,
                 __half* __restrict__ gout) {
    extern __shared__ char smem[];
    const uint32_t sb = smem_u32(smem);
    const int blocks_per_b = DINNER / 64;
    const int b     = blockIdx.x / blocks_per_b;
    const int cbase = (blockIdx.x % blocks_per_b) * 64;
    const int tid   = threadIdx.x;
    const int c     = cbase + tid;
    const size_t tok0 = (size_t)b * LL;

    float A[DSTATE];
    #pragma unroll
    for (int s = 0; s < DSTATE; s++) A[s] = -__expf(A_log[c * DSTATE + s]);
    const float a1 = A[0];
    bool pat = true;
    #pragma unroll
    for (int s = 0; s < DSTATE; s++)
        pat = pat && (fabsf(A[s] - (float)(s + 1) * a1) <= 1e-5f * fabsf(A[s]));
    const float Dv = Dp[c];
    float h[DSTATE];
    #pragma unroll
    for (int s = 0; s < DSTATE; s++) h[s] = 0.f;

    auto stage_load = [&](int st, int l0) {
        uint32_t base = sb + st * SSTG;
        #pragma unroll
        for (int u0 = 0; u0 < 12; u0++) {
            int u = u0 * 64 + tid;
            uint32_t dst; const void* src;
            if (u < 256) {               // delta [16][64] fp32
                int r = u >> 4, s = u & 15;
                dst = base + r * 256 + s * 16;
                src = delta + (tok0 + l0 + r) * DINNER + cbase + s * 4;
            } else if (u < 512) {        // z [16][64] fp32 (from xz)
                int v = u - 256; int r = v >> 4, s = v & 15;
                dst = base + 4096 + r * 256 + s * 16;
                src = xz + (tok0 + l0 + r) * (2 * DINNER) + DINNER + cbase + s * 4;
            } else if (u < 640) {        // bc [16][32] fp32
                int v = u - 512; int r = v >> 3, s = v & 7;
                dst = base + 8192 + r * 128 + s * 16;
                src = dbc + (tok0 + l0 + r) * DBC_W + DTRANK + s * 4;
            } else {                     // xi [16][64] fp16
                int v = u - 640; int r = v >> 3, s = v & 7;
                dst = base + 10240 + r * 128 + s * 16;
                src = xi + (tok0 + l0 + r) * DINNER + cbase + s * 8;
            }
            cp16(dst, src);
        }
    };

    const int nch = LL / SCHUNK;       // 128
    stage_load(0, 0);          CP_COMMIT();
    stage_load(1, SCHUNK);     CP_COMMIT();
    stage_load(2, 2 * SCHUNK); CP_COMMIT();

    for (int ck = 0; ck < nch; ck++) {
        CP_WAIT(2);
        __syncthreads();
        if (ck + 3 < nch) stage_load((ck + 3) & 3, (ck + 3) * SCHUNK);
        CP_COMMIT();

        const char* base = smem + (ck & 3) * SSTG;
        const float*  sd  = (const float*)(base);
        const float*  szv = (const float*)(base + 4096);
        const float*  sbc = (const float*)(base + 8192);
        const __half* sxi = (const __half*)(base + 10240);
        const int l0 = ck * SCHUNK;

        #pragma unroll 4
        for (int l = 0; l < SCHUNK; l++) {
            float d  = sd[l * 64 + tid];
            float zv = szv[l * 64 + tid];
            float xv = __half2float(sxi[l * 64 + tid]);
            const float* Bv = sbc + l * 32;
            const float* Cv = Bv + DSTATE;
            float dx = d * xv;
            float y = 0.f;
            if (pat) {
                float E  = __expf(d * a1);
                float E2 = E * E, E4 = E2 * E2, E8 = E4 * E4;
                float P[DSTATE];
                P[0]=E;      P[1]=E2;      P[2]=E2*E;      P[3]=E4;
                P[4]=E4*E;   P[5]=E4*E2;   P[6]=E4*P[2];   P[7]=E8;
                P[8]=E8*E;   P[9]=E8*E2;   P[10]=E8*P[2];  P[11]=E8*E4;
                P[12]=E8*P[4]; P[13]=E8*P[5]; P[14]=E8*P[6]; P[15]=E8*E8;
                #pragma unroll
                for (int s = 0; s < DSTATE; s++) {
                    h[s] = P[s] * h[s] + dx * Bv[s];
                    y = fmaf(h[s], Cv[s], y);
                }
            } else {
                #pragma unroll
                for (int s = 0; s < DSTATE; s++) {
                    float dA = __expf(d * A[s]);
                    h[s] = dA * h[s] + dx * Bv[s];
                    y = fmaf(h[s], Cv[s], y);
                }
            }
            float g  = y + xv * Dv;
            float sg = zv / (1.f + __expf(-zv));
            gout[(tok0 + l0 + l) * DINNER + c] = __float2half(g * sg);
        }
        __syncthreads();   // all consumed before next iter's prefetch overwrites
    }
}

// ---------------------------------------------------------------------------
// Launch
// ---------------------------------------------------------------------------
extern "C" void kernel_launch(void* const* d_in, const int* in_sizes, int n_in,
                              void* d_out, int out_size) {
    const float* x        = (const float*)d_in[0];
    const float* rms_w    = (const float*)d_in[1];
    const float* in_proj  = (const float*)d_in[2];
    const float* conv_w   = (const float*)d_in[3];
    const float* conv_b   = (const float*)d_in[4];
    const float* x_proj   = (const float*)d_in[5];
    const float* dt_w     = (const float*)d_in[6];
    const float* dt_b     = (const float*)d_in[7];
    const float* A_log    = (const float*)d_in[8];
    const float* Dp       = (const float*)d_in[9];
    const float* out_proj = (const float*)d_in[10];
    float* out = (float*)d_out;

    float *xz, *dbc, *delta;
    __half *xn, *xi, *dt, *gg;
    __half *ipTh, *ipTl, *xpTh, *xpTl, *dwTh, *dwTl, *opTh, *opTl;
    cudaGetSymbolAddress((void**)&xz,    g_xz);
    cudaGetSymbolAddress((void**)&dbc,   g_dbc);
    cudaGetSymbolAddress((void**)&delta, g_delta);
    cudaGetSymbolAddress((void**)&xn,    g_xn);
    cudaGetSymbolAddress((void**)&xi,    g_xi);
    cudaGetSymbolAddress((void**)&dt,    g_dt);
    cudaGetSymbolAddress((void**)&gg,    g_g);
    cudaGetSymbolAddress((void**)&ipTh,  g_ipTh);
    cudaGetSymbolAddress((void**)&ipTl,  g_ipTl);
    cudaGetSymbolAddress((void**)&xpTh,  g_xpTh);
    cudaGetSymbolAddress((void**)&xpTl,  g_xpTl);
    cudaGetSymbolAddress((void**)&dwTh,  g_dwTh);
    cudaGetSymbolAddress((void**)&dwTl,  g_dwTl);
    cudaGetSymbolAddress((void**)&opTh,  g_opTh);
    cudaGetSymbolAddress((void**)&opTl,  g_opTl);

    cudaFuncSetAttribute(mma_gemm<0>, cudaFuncAttributeMaxDynamicSharedMemorySize, SMEM_GEMM);
    cudaFuncSetAttribute(mma_gemm<1>, cudaFuncAttributeMaxDynamicSharedMemorySize, SMEM_GEMM);
    cudaFuncSetAttribute(mma_gemm<2>, cudaFuncAttributeMaxDynamicSharedMemorySize, SMEM_GEMM);
    cudaFuncSetAttribute(mma_gemm<3>, cudaFuncAttributeMaxDynamicSharedMemorySize, SMEM_GEMM);
    cudaFuncSetAttribute(scan_kernel, cudaFuncAttributeMaxDynamicSharedMemorySize, SCAN_SMEM);

    // 0. weight prep (transpose + hi/lo split)
    { dim3 g(2 * DINNER / 32, DIM / 32);   transpose_split<<<g, dim3(32, 8)>>>(in_proj,  ipTh, ipTl, DIM,    2 * DINNER); }
    { dim3 g(3, DINNER / 32);              transpose_split<<<g, dim3(32, 8)>>>(x_proj,   xpTh, xpTl, DINNER, DBC_W); }
    { dim3 g(DINNER / 32, DTRANK / 32);    transpose_split<<<g, dim3(32, 8)>>>(dt_w,     dwTh, dwTl, DTRANK, DINNER); }
    { dim3 g(DIM / 32, DINNER / 32);       transpose_split<<<g, dim3(32, 8)>>>(out_proj, opTh, opTl, DINNER, DIM); }

    // 1. RMSNorm -> xn fp16
    rmsnorm_kernel<<<NTOK, 256>>>(x, rms_w, xn);

    // 2. xz = xn @ in_proj  [8192 x 4096], K=1024
    {
        dim3 grid(2 * DINNER / 128, NTOK / 128);
        mma_gemm<0><<<grid, 256, SMEM_GEMM>>>(xn, ipTh, ipTl, xz,
                                              2 * DINNER, DIM, nullptr, nullptr);
    }

    // 3. conv + silu -> xi fp16
    {
        size_t n = (size_t)NTOK * DINNER;
        conv_silu_kernel<<<(unsigned)((n + 255) / 256), 256>>>(xz, conv_w, conv_b, xi);
    }

    // 4. dbc = xi @ x_proj  [8192 x 96], K=2048 ; dt cols -> fp16
    {
        dim3 grid(1, NTOK / 128);
        mma_gemm<3><<<grid, 256, SMEM_GEMM>>>(xi, xpTh, xpTl, dbc,
                                              DBC_W, DINNER, nullptr, dt);
    }

    // 5. delta = softplus(dt @ dt_w + dt_b)  [8192 x 2048], K=64
    {
        dim3 grid(DINNER / 128, NTOK / 128);
        mma_gemm<1><<<grid, 256, SMEM_GEMM>>>(dt, dwTh, dwTl, delta,
                                              DINNER, DTRANK, dt_b, nullptr);
    }

    // 6. selective scan + D skip + gate -> gated fp16
    scan_kernel<<<BB * (DINNER / 64), 64, SCAN_SMEM>>>(dbc, delta, xi, xz, A_log, Dp, gg);

    // 7. out = x + gated @ out_proj  [8192 x 1024], K=2048
    {
        dim3 grid(DIM / 128, NTOK / 128);
        mma_gemm<2><<<grid, 256, SMEM_GEMM>>>(gg, opTh, opTl, out,
                                              DIM, DINNER, x, nullptr);
    }
}